// round 13
// baseline (speedup 1.0000x reference)
#include <cuda_runtime.h>
#include <math.h>
#include <stdint.h>

// Problem sizes (fixed by the reference)
#define BB 64      // batch
#define TT 32      // timesteps
#define EE 512     // embed dim
#define HH 512     // hidden
#define H4 2048    // 4*H
#define VV 10000   // vocab

// ---------------- scratch (device globals: allocation-free) ----------------
__device__ __align__(16) float g_X[TT * BB * EE];        // [T][B][E]
__device__ __align__(16) float g_xproj[TT * BB * H4];    // [T][B][4H]
__device__ __align__(16) float g_hseq[TT * BB * HH];     // [T][B][H]
__device__ __align__(16) float g_h[BB * HH];
__device__ __align__(16) float g_c[BB * HH];
__device__ int g_cap64;

// ---------------- PTX helpers: packed fp32 (Blackwell f32x2) ---------------
__device__ __forceinline__ uint32_t smem_u32(const void* p) {
    uint32_t a;
    asm("{ .reg .u64 t; cvta.to.shared.u64 t, %1; cvt.u32.u64 %0, t; }"
        : "=r"(a) : "l"(p));
    return a;
}
__device__ __forceinline__ uint64_t splat2(float x) {
    uint64_t r;
    asm("mov.b64 %0, {%1, %1};" : "=l"(r) : "f"(x));
    return r;
}
__device__ __forceinline__ void ffma2(uint64_t& d, uint64_t a, uint64_t b) {
    asm("fma.rn.f32x2 %0, %1, %2, %0;" : "+l"(d) : "l"(a), "l"(b));
}
__device__ __forceinline__ void unpack2(uint64_t v, float& lo, float& hi) {
    asm("mov.b64 {%0, %1}, %2;" : "=f"(lo), "=f"(hi) : "l"(v));
}

// ---------------- captions dtype detection (int32 vs int64) ----------------
// For int64 (values < 10000) every high word is 0; for int32 the odd words
// are random ids. Reads only the first 2048 int32 words (in-bounds either way).
__global__ void detect_cap_kernel(const int* __restrict__ cap32) {
    if (threadIdx.x == 0 && blockIdx.x == 0) {
        int acc = 0;
        for (int i = 0; i < 256; i++) acc |= cap32[2 * i + 1];
        g_cap64 = (acc == 0) ? 1 : 0;
    }
}

// ---------------- build X: t=0 -> features, t>=1 -> embed(captions[:,t]) ----
__global__ void build_x_kernel(const float* __restrict__ feat,
                               const void* __restrict__ cap,
                               const float* __restrict__ embW) {
    int row = blockIdx.x;            // row = t*B + b
    int t = row >> 6;
    int b = row & 63;
    const float* src;
    if (t == 0) {
        src = feat + (size_t)b * EE;
    } else {
        long long idx;
        if (g_cap64) idx = ((const long long*)cap)[b * TT + t];
        else         idx = (long long)((const int*)cap)[b * TT + t];
        src = embW + (size_t)idx * EE;
    }
    float4* dst = (float4*)(g_X + (size_t)row * EE);
    const float4* s4 = (const float4*)src;
    for (int i = threadIdx.x; i < EE / 4; i += blockDim.x) dst[i] = s4[i];
}

// ---------------- f32x2 SGEMM NT: C = A[M,K] * B[N,K]^T (+ biases) ---------
// R5's proven 128x128x16 tile / 256 thr / 8x8 microtile, with the inner
// product converted to packed fp32 (FFMA2): 32 FFMA2 replace 64 FFMA per
// k-step. Accumulators live as 32 x u64 (f32x2 pairs over the j dimension);
// B fragments loaded as b64 pairs directly (ld.shared.v2.u64).
// asel: 0 -> A = g_X, 1 -> A = g_hseq.
// mode: 0 -> C[m*N+n]; 1 -> C[(b*TT+t)*N+n] with m = t*64+b.
#define BM 128
#define BN 128
#define BK 16

__global__ __launch_bounds__(256) void sgemm2_nt_kernel(
    int asel, const float* __restrict__ Bm,
    const float* __restrict__ bias1, const float* __restrict__ bias2,
    float* __restrict__ C, int M, int N, int K, int mode)
{
    const float* __restrict__ A = (asel == 0) ? g_X : g_hseq;

    // Row stride BM+4 = 132 floats = 528B (16B multiple: float4/b64-safe).
    __shared__ float As[2][BK][BM + 4];
    __shared__ float Bs[2][BK][BN + 4];

    const int tid = threadIdx.x;
    const int bm = blockIdx.y * BM;
    const int bn = blockIdx.x * BN;

    const int lr = tid >> 2;           // 0..63
    const int lk = (tid & 3) << 2;     // 0,4,8,12

    const int tx = tid & 15;
    const int ty = tid >> 4;

    const uint32_t bs0 = smem_u32(&Bs[0][0][0]);

    // acc2[i][jp]: row i (0..7), column pair jp (cols 2jp, 2jp+1); lo = 2jp.
    uint64_t acc2[8][4];
#pragma unroll
    for (int i = 0; i < 8; i++)
#pragma unroll
        for (int jp = 0; jp < 4; jp++) acc2[i][jp] = 0ull;

    float4 ra0, ra1, rb0, rb1;
    const float4 z4 = make_float4(0.f, 0.f, 0.f, 0.f);

#define FETCH(K0)                                                              \
    do {                                                                       \
        ra0 = *(const float4*)(A + (size_t)(bm + lr) * K + (K0) + lk);         \
        ra1 = *(const float4*)(A + (size_t)(bm + lr + 64) * K + (K0) + lk);    \
        int r0_ = bn + lr, r1_ = bn + lr + 64;                                 \
        rb0 = (r0_ < N) ? *(const float4*)(Bm + (size_t)r0_ * K + (K0) + lk) : z4; \
        rb1 = (r1_ < N) ? *(const float4*)(Bm + (size_t)r1_ * K + (K0) + lk) : z4; \
    } while (0)

#define STAGE(BUF)                                                             \
    do {                                                                       \
        As[BUF][lk + 0][lr] = ra0.x; As[BUF][lk + 1][lr] = ra0.y;              \
        As[BUF][lk + 2][lr] = ra0.z; As[BUF][lk + 3][lr] = ra0.w;              \
        As[BUF][lk + 0][lr + 64] = ra1.x; As[BUF][lk + 1][lr + 64] = ra1.y;    \
        As[BUF][lk + 2][lr + 64] = ra1.z; As[BUF][lk + 3][lr + 64] = ra1.w;    \
        Bs[BUF][lk + 0][lr] = rb0.x; Bs[BUF][lk + 1][lr] = rb0.y;              \
        Bs[BUF][lk + 2][lr] = rb0.z; Bs[BUF][lk + 3][lr] = rb0.w;              \
        Bs[BUF][lk + 0][lr + 64] = rb1.x; Bs[BUF][lk + 1][lr + 64] = rb1.y;    \
        Bs[BUF][lk + 2][lr + 64] = rb1.z; Bs[BUF][lk + 3][lr + 64] = rb1.w;    \
    } while (0)

    FETCH(0);
    STAGE(0);
    __syncthreads();

    const int nk = K / BK;
    for (int kt = 0; kt < nk; kt++) {
        if (kt + 1 < nk) FETCH((kt + 1) * BK);
        const int buf = kt & 1;
        // byte offset of Bs[buf][0][tx*8] from Bs[0][0][0]
        const uint32_t bbase =
            bs0 + ((uint32_t)(buf * BK * (BN + 4) + tx * 8) << 2);
#pragma unroll
        for (int kk = 0; kk < BK; kk++) {
            float4 a0 = *(const float4*)&As[buf][kk][ty * 8];
            float4 a1 = *(const float4*)&As[buf][kk][ty * 8 + 4];
            // B column pairs: 4 x b64 (16B-aligned: kk*528 + tx*32)
            uint64_t bp[4];
            uint32_t baddr = bbase + (uint32_t)(kk * (BN + 4)) * 4u;
            asm("ld.shared.v2.u64 {%0, %1}, [%2];"
                : "=l"(bp[0]), "=l"(bp[1]) : "r"(baddr));
            asm("ld.shared.v2.u64 {%0, %1}, [%2];"
                : "=l"(bp[2]), "=l"(bp[3]) : "r"(baddr + 16));
            float av[8] = {a0.x, a0.y, a0.z, a0.w, a1.x, a1.y, a1.z, a1.w};
#pragma unroll
            for (int i = 0; i < 8; i++) {
                uint64_t ap = splat2(av[i]);
#pragma unroll
                for (int jp = 0; jp < 4; jp++) ffma2(acc2[i][jp], ap, bp[jp]);
            }
        }
        if (kt + 1 < nk) {
            __syncthreads();
            STAGE((kt + 1) & 1);
            __syncthreads();
        }
    }

#pragma unroll
    for (int i = 0; i < 8; i++) {
        int m = bm + ty * 8 + i;
        int t = m >> 6;
        int b = m & 63;
#pragma unroll
        for (int jp = 0; jp < 4; jp++) {
            float vlo, vhi;
            unpack2(acc2[i][jp], vlo, vhi);
            float vv[2] = {vlo, vhi};
#pragma unroll
            for (int s = 0; s < 2; s++) {
                int n = bn + tx * 8 + jp * 2 + s;
                if (n < N) {
                    float v = vv[s];
                    if (bias1) v += bias1[n];
                    if (bias2) v += bias2[n];
                    if (mode == 0) C[(size_t)m * N + n] = v;
                    else           C[(size_t)(b * TT + t) * N + n] = v;
                }
            }
        }
    }
#undef FETCH
#undef STAGE
}

// ---------------- fused LSTM step: matvec + gates + update, 1 kernel -------
// Block bx (128 blocks) owns hidden units u0 = bx*4 -> 16 gate rows of W_hh.
// R13: K chunk 32 -> 64 (halves the serial load/sync phases; kernel is
// latency-bound at issue=7%).
__global__ __launch_bounds__(256) void lstm_step_kernel(
    const float* __restrict__ Whh, int t)
{
    const int u0 = blockIdx.x * 4;
    const int tid = threadIdx.x;
    const int tx = tid & 15;   // gate-row index r: g = tx>>2, j = tx&3
    const int ty = tid >> 4;   // batch quad

    __shared__ float hs[64][68];   // stride 68 floats = 272B (16B multiple)
    __shared__ float ws[64][20];
    __shared__ float gsm[16][68];

    float a0 = 0.f, a1 = 0.f, a2 = 0.f, a3 = 0.f;

    if (t > 0) {
        for (int k0 = 0; k0 < HH; k0 += 64) {
            // h chunk [64 b][64 k] -> hs[kk][b]
            for (int i = tid; i < 64 * 64; i += 256) {
                int b = i >> 6, kk = i & 63;
                hs[kk][b] = g_h[b * HH + k0 + kk];
            }
            // W chunk: 16 selected gate rows x 64 k
            for (int i = tid; i < 16 * 64; i += 256) {
                int r = i >> 6, kk = i & 63;
                int grow = (r >> 2) * HH + u0 + (r & 3);
                ws[kk][r] = Whh[(size_t)grow * HH + k0 + kk];
            }
            __syncthreads();
#pragma unroll 16
            for (int kk = 0; kk < 64; kk++) {
                float w = ws[kk][tx];                        // bcast per tx
                float4 hv = *(const float4*)&hs[kk][ty * 4]; // bcast per ty
                a0 += hv.x * w;
                a1 += hv.y * w;
                a2 += hv.z * w;
                a3 += hv.w * w;
            }
            __syncthreads();
        }
    }

    gsm[tx][ty * 4 + 0] = a0;
    gsm[tx][ty * 4 + 1] = a1;
    gsm[tx][ty * 4 + 2] = a2;
    gsm[tx][ty * 4 + 3] = a3;
    __syncthreads();

    const int j = tid & 3;
    const int b = tid >> 2;
    const int u = u0 + j;

    const float* xp = g_xproj + ((size_t)(t * BB + b)) * H4;
    float gi = xp[u]           + gsm[0 * 4 + j][b];
    float gf = xp[HH + u]      + gsm[1 * 4 + j][b];
    float gg = xp[2 * HH + u]  + gsm[2 * 4 + j][b];
    float go = xp[3 * HH + u]  + gsm[3 * 4 + j][b];

    float i_g = 1.0f / (1.0f + expf(-gi));
    float f_g = 1.0f / (1.0f + expf(-gf));
    float g_g = tanhf(gg);
    float o_g = 1.0f / (1.0f + expf(-go));

    const int idx = b * HH + u;
    float c_old = (t > 0) ? g_c[idx] : 0.0f;
    float c = f_g * c_old + i_g * g_g;
    float h = o_g * tanhf(c);
    g_c[idx] = c;
    g_h[idx] = h;
    g_hseq[((size_t)(t * BB + b)) * HH + u] = h;
}

// ---------------- launch ----------------
extern "C" void kernel_launch(void* const* d_in, const int* in_sizes, int n_in,
                              void* d_out, int out_size)
{
    const float* features = (const float*)d_in[0];
    const void*  captions = d_in[1];                 // int32 or int64, detected
    const float* embed_W  = (const float*)d_in[2];
    const float* W_ih     = (const float*)d_in[3];
    const float* W_hh     = (const float*)d_in[4];
    const float* b_ih     = (const float*)d_in[5];
    const float* b_hh     = (const float*)d_in[6];
    const float* fc_W     = (const float*)d_in[7];
    const float* fc_b     = (const float*)d_in[8];
    float* out = (float*)d_out;

    // Resolve device address of g_xproj once (host-side symbol lookup;
    // allocation-free, graph-safe).
    static float* xproj_ptr = nullptr;
    if (!xproj_ptr) {
        void* p = nullptr;
        cudaGetSymbolAddress(&p, g_xproj);
        xproj_ptr = (float*)p;
    }

    detect_cap_kernel<<<1, 32>>>((const int*)captions);
    build_x_kernel<<<TT * BB, 128>>>(features, captions, embed_W);

    // x_proj = X @ W_ih^T + b_ih + b_hh   [T*B, 4H]   (f32x2 FFMA2)
    sgemm2_nt_kernel<<<dim3(H4 / BN, (TT * BB) / BM), 256>>>(
        0, W_ih, b_ih, b_hh, xproj_ptr, TT * BB, H4, EE, 0);

    // fused recurrence: one kernel per timestep
    for (int t = 0; t < TT; t++)
        lstm_step_kernel<<<128, 256>>>(W_hh, t);

    // logits: out[b][t][v] = h_seq[t][b] . fc_W[v] + fc_b[v]   (f32x2)
    sgemm2_nt_kernel<<<dim3((VV + BN - 1) / BN, (TT * BB) / BM), 256>>>(
        1, fc_W, fc_b, nullptr, out, TT * BB, VV, HH, 1);
}

// round 14
// speedup vs baseline: 1.0275x; 1.0275x over previous
#include <cuda_runtime.h>
#include <math.h>
#include <stdint.h>

// Problem sizes (fixed by the reference)
#define BB 64      // batch
#define TT 32      // timesteps
#define EE 512     // embed dim
#define HH 512     // hidden
#define H4 2048    // 4*H
#define VV 10000   // vocab

// ---------------- scratch (device globals: allocation-free) ----------------
__device__ __align__(16) float g_X[TT * BB * EE];        // [T][B][E]
__device__ __align__(16) float g_xproj[TT * BB * H4];    // [T][B][4H]
__device__ __align__(16) float g_hseq[TT * BB * HH];     // [T][B][H]
__device__ __align__(16) float g_h[BB * HH];
__device__ __align__(16) float g_c[BB * HH];
__device__ int g_cap64;

// ---------------- captions dtype detection (int32 vs int64) ----------------
// For int64 (values < 10000) every high word is 0; for int32 the odd words
// are random ids. Reads only the first 2048 int32 words (in-bounds either way).
__global__ void detect_cap_kernel(const int* __restrict__ cap32) {
    if (threadIdx.x == 0 && blockIdx.x == 0) {
        int acc = 0;
        for (int i = 0; i < 256; i++) acc |= cap32[2 * i + 1];
        g_cap64 = (acc == 0) ? 1 : 0;
    }
}

// ---------------- build X: t=0 -> features, t>=1 -> embed(captions[:,t]) ----
__global__ void build_x_kernel(const float* __restrict__ feat,
                               const void* __restrict__ cap,
                               const float* __restrict__ embW) {
    int row = blockIdx.x;            // row = t*B + b
    int t = row >> 6;
    int b = row & 63;
    const float* src;
    if (t == 0) {
        src = feat + (size_t)b * EE;
    } else {
        long long idx;
        if (g_cap64) idx = ((const long long*)cap)[b * TT + t];
        else         idx = (long long)((const int*)cap)[b * TT + t];
        src = embW + (size_t)idx * EE;
    }
    float4* dst = (float4*)(g_X + (size_t)row * EE);
    const float4* s4 = (const float4*)src;
    for (int i = threadIdx.x; i < EE / 4; i += blockDim.x) dst[i] = s4[i];
}

// ---------------- SGEMM NT: C[M,N] = A[M,K] * B[N,K]^T (+ biases) ----------
// R14: identical tile/smem/data-path to the proven R5 kernel (28 TF/s,
// issue 53.6% > fma 38.5% -> latency-bound at 8 warps/SM), but 512 threads
// with an 8x4 microtile: per-thread regs ~139 -> ~75 naturally (no forced
// launch_bounds -> no spills), warps/SM 8 -> 16 to hide LDS latency.
// Thread map: ty = tid>>4 (0..31) -> 4 M-rows ty*4; tx = tid&15 -> 8 N-cols
// tx*8 (same proven B access pattern as before).
// asel: 0 -> A = g_X, 1 -> A = g_hseq.
// mode: 0 -> C[m*N+n]; 1 -> C[(b*TT+t)*N+n] with m = t*64+b.
#define BM 128
#define BN 128
#define BK 16

__global__ __launch_bounds__(512) void sgemm_nt_kernel(
    int asel, const float* __restrict__ Bm,
    const float* __restrict__ bias1, const float* __restrict__ bias2,
    float* __restrict__ C, int M, int N, int K, int mode)
{
    const float* __restrict__ A = (asel == 0) ? g_X : g_hseq;

    // Row stride BM+4 = 132 floats = 528B: 16B multiple, float4-safe.
    __shared__ float As[2][BK][BM + 4];
    __shared__ float Bs[2][BK][BN + 4];

    const int tid = threadIdx.x;
    const int bm = blockIdx.y * BM;
    const int bn = blockIdx.x * BN;

    // loader mapping: 512 threads, each stages 1 float4 of A and of B
    const int lr = tid >> 2;           // 0..127
    const int lk = (tid & 3) << 2;     // 0,4,8,12

    // compute mapping: 32(M) x 16(N) threads, 4x8 micro-tile
    const int tx = tid & 15;
    const int ty = tid >> 4;

    float acc[4][8];
#pragma unroll
    for (int i = 0; i < 4; i++)
#pragma unroll
        for (int j = 0; j < 8; j++) acc[i][j] = 0.0f;

    float4 ra0, rb0;
    const float4 z4 = make_float4(0.f, 0.f, 0.f, 0.f);

#define FETCH(K0)                                                              \
    do {                                                                       \
        ra0 = *(const float4*)(A + (size_t)(bm + lr) * K + (K0) + lk);         \
        int r0_ = bn + lr;                                                     \
        rb0 = (r0_ < N) ? *(const float4*)(Bm + (size_t)r0_ * K + (K0) + lk) : z4; \
    } while (0)

#define STAGE(BUF)                                                             \
    do {                                                                       \
        As[BUF][lk + 0][lr] = ra0.x; As[BUF][lk + 1][lr] = ra0.y;              \
        As[BUF][lk + 2][lr] = ra0.z; As[BUF][lk + 3][lr] = ra0.w;              \
        Bs[BUF][lk + 0][lr] = rb0.x; Bs[BUF][lk + 1][lr] = rb0.y;              \
        Bs[BUF][lk + 2][lr] = rb0.z; Bs[BUF][lk + 3][lr] = rb0.w;              \
    } while (0)

    FETCH(0);
    STAGE(0);
    __syncthreads();

    const int nk = K / BK;
    for (int kt = 0; kt < nk; kt++) {
        if (kt + 1 < nk) FETCH((kt + 1) * BK);
        const int buf = kt & 1;
#pragma unroll
        for (int kk = 0; kk < BK; kk++) {
            float4 a0 = *(const float4*)&As[buf][kk][ty * 4];
            float4 b0 = *(const float4*)&Bs[buf][kk][tx * 8];
            float4 b1 = *(const float4*)&Bs[buf][kk][tx * 8 + 4];
            float av[4] = {a0.x, a0.y, a0.z, a0.w};
            float bv[8] = {b0.x, b0.y, b0.z, b0.w, b1.x, b1.y, b1.z, b1.w};
#pragma unroll
            for (int i = 0; i < 4; i++)
#pragma unroll
                for (int j = 0; j < 8; j++) acc[i][j] += av[i] * bv[j];
        }
        if (kt + 1 < nk) {
            __syncthreads();
            STAGE((kt + 1) & 1);
            __syncthreads();
        }
    }

#pragma unroll
    for (int i = 0; i < 4; i++) {
        int m = bm + ty * 4 + i;
        int t = m >> 6;
        int b = m & 63;
#pragma unroll
        for (int j = 0; j < 8; j++) {
            int n = bn + tx * 8 + j;
            if (n < N) {
                float v = acc[i][j];
                if (bias1) v += bias1[n];
                if (bias2) v += bias2[n];
                if (mode == 0) C[(size_t)m * N + n] = v;
                else           C[(size_t)(b * TT + t) * N + n] = v;
            }
        }
    }
#undef FETCH
#undef STAGE
}

// ---------------- fused LSTM step: matvec + gates + update, 1 kernel -------
// Block bx (128 blocks) owns hidden units u0 = bx*4 -> 16 gate rows of W_hh.
// EXACT R8-measured version (4.77 us/step, chunk 32) — R13's chunk-64
// variant regressed to 6.24 us and is reverted.
__global__ __launch_bounds__(256) void lstm_step_kernel(
    const float* __restrict__ Whh, int t)
{
    const int u0 = blockIdx.x * 4;
    const int tid = threadIdx.x;
    const int tx = tid & 15;   // gate-row index r: g = tx>>2, j = tx&3
    const int ty = tid >> 4;   // batch quad

    __shared__ float hs[32][68];   // stride 68 floats = 272B (16B multiple)
    __shared__ float ws[32][20];
    __shared__ float gsm[16][68];

    float a0 = 0.f, a1 = 0.f, a2 = 0.f, a3 = 0.f;

    if (t > 0) {
        for (int k0 = 0; k0 < HH; k0 += 32) {
            for (int i = tid; i < 64 * 32; i += 256) {
                int b = i >> 5, kk = i & 31;
                hs[kk][b] = g_h[b * HH + k0 + kk];
            }
            for (int i = tid; i < 16 * 32; i += 256) {
                int r = i >> 5, kk = i & 31;
                int grow = (r >> 2) * HH + u0 + (r & 3);
                ws[kk][r] = Whh[(size_t)grow * HH + k0 + kk];
            }
            __syncthreads();
#pragma unroll
            for (int kk = 0; kk < 32; kk++) {
                float w = ws[kk][tx];                        // bcast per tx
                float4 hv = *(const float4*)&hs[kk][ty * 4]; // bcast per ty
                a0 += hv.x * w;
                a1 += hv.y * w;
                a2 += hv.z * w;
                a3 += hv.w * w;
            }
            __syncthreads();
        }
    }

    gsm[tx][ty * 4 + 0] = a0;
    gsm[tx][ty * 4 + 1] = a1;
    gsm[tx][ty * 4 + 2] = a2;
    gsm[tx][ty * 4 + 3] = a3;
    __syncthreads();

    const int j = tid & 3;
    const int b = tid >> 2;
    const int u = u0 + j;

    const float* xp = g_xproj + ((size_t)(t * BB + b)) * H4;
    float gi = xp[u]           + gsm[0 * 4 + j][b];
    float gf = xp[HH + u]      + gsm[1 * 4 + j][b];
    float gg = xp[2 * HH + u]  + gsm[2 * 4 + j][b];
    float go = xp[3 * HH + u]  + gsm[3 * 4 + j][b];

    float i_g = 1.0f / (1.0f + expf(-gi));
    float f_g = 1.0f / (1.0f + expf(-gf));
    float g_g = tanhf(gg);
    float o_g = 1.0f / (1.0f + expf(-go));

    const int idx = b * HH + u;
    float c_old = (t > 0) ? g_c[idx] : 0.0f;
    float c = f_g * c_old + i_g * g_g;
    float h = o_g * tanhf(c);
    g_c[idx] = c;
    g_h[idx] = h;
    g_hseq[((size_t)(t * BB + b)) * HH + u] = h;
}

// ---------------- launch ----------------
extern "C" void kernel_launch(void* const* d_in, const int* in_sizes, int n_in,
                              void* d_out, int out_size)
{
    const float* features = (const float*)d_in[0];
    const void*  captions = d_in[1];                 // int32 or int64, detected
    const float* embed_W  = (const float*)d_in[2];
    const float* W_ih     = (const float*)d_in[3];
    const float* W_hh     = (const float*)d_in[4];
    const float* b_ih     = (const float*)d_in[5];
    const float* b_hh     = (const float*)d_in[6];
    const float* fc_W     = (const float*)d_in[7];
    const float* fc_b     = (const float*)d_in[8];
    float* out = (float*)d_out;

    // Resolve device address of g_xproj once (host-side symbol lookup;
    // allocation-free, graph-safe).
    static float* xproj_ptr = nullptr;
    if (!xproj_ptr) {
        void* p = nullptr;
        cudaGetSymbolAddress(&p, g_xproj);
        xproj_ptr = (float*)p;
    }

    detect_cap_kernel<<<1, 32>>>((const int*)captions);
    build_x_kernel<<<TT * BB, 128>>>(features, captions, embed_W);

    // x_proj = X @ W_ih^T + b_ih + b_hh   [T*B, 4H]
    sgemm_nt_kernel<<<dim3(H4 / BN, (TT * BB) / BM), 512>>>(
        0, W_ih, b_ih, b_hh, xproj_ptr, TT * BB, H4, EE, 0);

    // fused recurrence: one kernel per timestep (proven 4.77us/step version)
    for (int t = 0; t < TT; t++)
        lstm_step_kernel<<<128, 256>>>(W_hh, t);

    // logits: out[b][t][v] = h_seq[t][b] . fc_W[v] + fc_b[v]
    sgemm_nt_kernel<<<dim3((VV + BN - 1) / BN, (TT * BB) / BM), 512>>>(
        1, fc_W, fc_b, nullptr, out, TT * BB, VV, HH, 1);
}

// round 15
// speedup vs baseline: 1.2119x; 1.1794x over previous
#include <cuda_runtime.h>
#include <math.h>
#include <stdint.h>

// Problem sizes (fixed by the reference)
#define BB 64      // batch
#define TT 32      // timesteps
#define EE 512     // embed dim
#define HH 512     // hidden
#define H4 2048    // 4*H
#define VV 10000   // vocab

// ---------------- scratch (device globals: allocation-free) ----------------
__device__ __align__(16) float g_X[TT * BB * EE];        // [T][B][E]
__device__ __align__(16) float g_xproj[TT * BB * H4];    // [T][B][4H]
__device__ __align__(16) float g_hseq[TT * BB * HH];     // [T][B][H]
__device__ __align__(16) float g_h[BB * HH];
__device__ __align__(16) float g_c[BB * HH];
__device__ int g_cap64;

// ---------------- captions dtype detection (int32 vs int64) ----------------
// For int64 (values < 10000) every high word is 0; for int32 the odd words
// are random ids. Reads only the first 2048 int32 words (in-bounds either way).
__global__ void detect_cap_kernel(const int* __restrict__ cap32) {
    if (threadIdx.x == 0 && blockIdx.x == 0) {
        int acc = 0;
        for (int i = 0; i < 256; i++) acc |= cap32[2 * i + 1];
        g_cap64 = (acc == 0) ? 1 : 0;
    }
}

// ---------------- build X: t=0 -> features, t>=1 -> embed(captions[:,t]) ----
__global__ void build_x_kernel(const float* __restrict__ feat,
                               const void* __restrict__ cap,
                               const float* __restrict__ embW) {
    int row = blockIdx.x;            // row = t*B + b
    int t = row >> 6;
    int b = row & 63;
    const float* src;
    if (t == 0) {
        src = feat + (size_t)b * EE;
    } else {
        long long idx;
        if (g_cap64) idx = ((const long long*)cap)[b * TT + t];
        else         idx = (long long)((const int*)cap)[b * TT + t];
        src = embW + (size_t)idx * EE;
    }
    float4* dst = (float4*)(g_X + (size_t)row * EE);
    const float4* s4 = (const float4*)src;
    for (int i = threadIdx.x; i < EE / 4; i += blockDim.x) dst[i] = s4[i];
}

// ---------------- SGEMM NT: C[M,N] = A[M,K] * B[N,K]^T (+ biases) ----------
// EXACT byte-for-byte revert to the R5-measured kernel: 151us x_proj /
// ~700us logits, 28 TF/s, 256 thr, 8x8 microtile, regs=139, occ 12.5%.
// Every modification attempted since (launch-bounds min, 512-thr retile,
// tf32/fp16 mma, ldmatrix, FFMA2) regressed it — do not touch.
// asel: 0 -> A = g_X, 1 -> A = g_hseq.
// mode: 0 -> C[m*N+n]; 1 -> C[(b*TT+t)*N+n] with m = t*64+b.
#define BM 128
#define BN 128
#define BK 16

__global__ __launch_bounds__(256) void sgemm_nt_kernel(
    int asel, const float* __restrict__ Bm,
    const float* __restrict__ bias1, const float* __restrict__ bias2,
    float* __restrict__ C, int M, int N, int K, int mode)
{
    const float* __restrict__ A = (asel == 0) ? g_X : g_hseq;

    // Row stride BM+4 = 132 floats = 528 bytes: multiple of 16B, so float4
    // reads at &As[buf][kk][8*t] are always 16B-aligned.
    __shared__ float As[2][BK][BM + 4];
    __shared__ float Bs[2][BK][BN + 4];

    const int tid = threadIdx.x;
    const int bm = blockIdx.y * BM;
    const int bn = blockIdx.x * BN;

    const int lr = tid >> 2;           // 0..63
    const int lk = (tid & 3) << 2;     // 0,4,8,12

    const int tx = tid & 15;
    const int ty = tid >> 4;

    float acc[8][8];
#pragma unroll
    for (int i = 0; i < 8; i++)
#pragma unroll
        for (int j = 0; j < 8; j++) acc[i][j] = 0.0f;

    float4 ra0, ra1, rb0, rb1;
    const float4 z4 = make_float4(0.f, 0.f, 0.f, 0.f);

#define FETCH(K0)                                                              \
    do {                                                                       \
        ra0 = *(const float4*)(A + (size_t)(bm + lr) * K + (K0) + lk);         \
        ra1 = *(const float4*)(A + (size_t)(bm + lr + 64) * K + (K0) + lk);    \
        int r0_ = bn + lr, r1_ = bn + lr + 64;                                 \
        rb0 = (r0_ < N) ? *(const float4*)(Bm + (size_t)r0_ * K + (K0) + lk) : z4; \
        rb1 = (r1_ < N) ? *(const float4*)(Bm + (size_t)r1_ * K + (K0) + lk) : z4; \
    } while (0)

#define STAGE(BUF)                                                             \
    do {                                                                       \
        As[BUF][lk + 0][lr] = ra0.x; As[BUF][lk + 1][lr] = ra0.y;              \
        As[BUF][lk + 2][lr] = ra0.z; As[BUF][lk + 3][lr] = ra0.w;              \
        As[BUF][lk + 0][lr + 64] = ra1.x; As[BUF][lk + 1][lr + 64] = ra1.y;    \
        As[BUF][lk + 2][lr + 64] = ra1.z; As[BUF][lk + 3][lr + 64] = ra1.w;    \
        Bs[BUF][lk + 0][lr] = rb0.x; Bs[BUF][lk + 1][lr] = rb0.y;              \
        Bs[BUF][lk + 2][lr] = rb0.z; Bs[BUF][lk + 3][lr] = rb0.w;              \
        Bs[BUF][lk + 0][lr + 64] = rb1.x; Bs[BUF][lk + 1][lr + 64] = rb1.y;    \
        Bs[BUF][lk + 2][lr + 64] = rb1.z; Bs[BUF][lk + 3][lr + 64] = rb1.w;    \
    } while (0)

    FETCH(0);
    STAGE(0);
    __syncthreads();

    const int nk = K / BK;
    for (int kt = 0; kt < nk; kt++) {
        if (kt + 1 < nk) FETCH((kt + 1) * BK);
        const int buf = kt & 1;
#pragma unroll
        for (int kk = 0; kk < BK; kk++) {
            float4 a0 = *(const float4*)&As[buf][kk][ty * 8];
            float4 a1 = *(const float4*)&As[buf][kk][ty * 8 + 4];
            float4 b0 = *(const float4*)&Bs[buf][kk][tx * 8];
            float4 b1 = *(const float4*)&Bs[buf][kk][tx * 8 + 4];
            float av[8] = {a0.x, a0.y, a0.z, a0.w, a1.x, a1.y, a1.z, a1.w};
            float bv[8] = {b0.x, b0.y, b0.z, b0.w, b1.x, b1.y, b1.z, b1.w};
#pragma unroll
            for (int i = 0; i < 8; i++)
#pragma unroll
                for (int j = 0; j < 8; j++) acc[i][j] += av[i] * bv[j];
        }
        if (kt + 1 < nk) {
            __syncthreads();
            STAGE((kt + 1) & 1);
            __syncthreads();
        }
    }

#pragma unroll
    for (int i = 0; i < 8; i++) {
        int m = bm + ty * 8 + i;
        int t = m >> 6;
        int b = m & 63;
#pragma unroll
        for (int j = 0; j < 8; j++) {
            int n = bn + tx * 8 + j;
            if (n < N) {
                float v = acc[i][j];
                if (bias1) v += bias1[n];
                if (bias2) v += bias2[n];
                if (mode == 0) C[(size_t)m * N + n] = v;
                else           C[(size_t)(b * TT + t) * N + n] = v;
            }
        }
    }
#undef FETCH
#undef STAGE
}

// ---------------- fused LSTM step: matvec + gates + update, 1 kernel -------
// Block bx (128 blocks) owns hidden units u0 = bx*4 -> 16 gate rows of W_hh.
// EXACT R8/R14-measured version (4.8 us/step, chunk 32).
__global__ __launch_bounds__(256) void lstm_step_kernel(
    const float* __restrict__ Whh, int t)
{
    const int u0 = blockIdx.x * 4;
    const int tid = threadIdx.x;
    const int tx = tid & 15;   // gate-row index r: g = tx>>2, j = tx&3
    const int ty = tid >> 4;   // batch quad

    __shared__ float hs[32][68];   // stride 68 floats = 272B (16B multiple)
    __shared__ float ws[32][20];
    __shared__ float gsm[16][68];

    float a0 = 0.f, a1 = 0.f, a2 = 0.f, a3 = 0.f;

    if (t > 0) {
        for (int k0 = 0; k0 < HH; k0 += 32) {
            for (int i = tid; i < 64 * 32; i += 256) {
                int b = i >> 5, kk = i & 31;
                hs[kk][b] = g_h[b * HH + k0 + kk];
            }
            for (int i = tid; i < 16 * 32; i += 256) {
                int r = i >> 5, kk = i & 31;
                int grow = (r >> 2) * HH + u0 + (r & 3);
                ws[kk][r] = Whh[(size_t)grow * HH + k0 + kk];
            }
            __syncthreads();
#pragma unroll
            for (int kk = 0; kk < 32; kk++) {
                float w = ws[kk][tx];                        // bcast per tx
                float4 hv = *(const float4*)&hs[kk][ty * 4]; // bcast per ty
                a0 += hv.x * w;
                a1 += hv.y * w;
                a2 += hv.z * w;
                a3 += hv.w * w;
            }
            __syncthreads();
        }
    }

    gsm[tx][ty * 4 + 0] = a0;
    gsm[tx][ty * 4 + 1] = a1;
    gsm[tx][ty * 4 + 2] = a2;
    gsm[tx][ty * 4 + 3] = a3;
    __syncthreads();

    const int j = tid & 3;
    const int b = tid >> 2;
    const int u = u0 + j;

    const float* xp = g_xproj + ((size_t)(t * BB + b)) * H4;
    float gi = xp[u]           + gsm[0 * 4 + j][b];
    float gf = xp[HH + u]      + gsm[1 * 4 + j][b];
    float gg = xp[2 * HH + u]  + gsm[2 * 4 + j][b];
    float go = xp[3 * HH + u]  + gsm[3 * 4 + j][b];

    float i_g = 1.0f / (1.0f + expf(-gi));
    float f_g = 1.0f / (1.0f + expf(-gf));
    float g_g = tanhf(gg);
    float o_g = 1.0f / (1.0f + expf(-go));

    const int idx = b * HH + u;
    float c_old = (t > 0) ? g_c[idx] : 0.0f;
    float c = f_g * c_old + i_g * g_g;
    float h = o_g * tanhf(c);
    g_c[idx] = c;
    g_h[idx] = h;
    g_hseq[((size_t)(t * BB + b)) * HH + u] = h;
}

// ---------------- launch ----------------
extern "C" void kernel_launch(void* const* d_in, const int* in_sizes, int n_in,
                              void* d_out, int out_size)
{
    const float* features = (const float*)d_in[0];
    const void*  captions = d_in[1];                 // int32 or int64, detected
    const float* embed_W  = (const float*)d_in[2];
    const float* W_ih     = (const float*)d_in[3];
    const float* W_hh     = (const float*)d_in[4];
    const float* b_ih     = (const float*)d_in[5];
    const float* b_hh     = (const float*)d_in[6];
    const float* fc_W     = (const float*)d_in[7];
    const float* fc_b     = (const float*)d_in[8];
    float* out = (float*)d_out;

    // Resolve device address of g_xproj once (host-side symbol lookup;
    // allocation-free, graph-safe).
    static float* xproj_ptr = nullptr;
    if (!xproj_ptr) {
        void* p = nullptr;
        cudaGetSymbolAddress(&p, g_xproj);
        xproj_ptr = (float*)p;
    }

    detect_cap_kernel<<<1, 32>>>((const int*)captions);
    build_x_kernel<<<TT * BB, 128>>>(features, captions, embed_W);

    // x_proj = X @ W_ih^T + b_ih + b_hh   [T*B, 4H]
    sgemm_nt_kernel<<<dim3(H4 / BN, (TT * BB) / BM), 256>>>(
        0, W_ih, b_ih, b_hh, xproj_ptr, TT * BB, H4, EE, 0);

    // fused recurrence: one kernel per timestep (proven 4.8us/step)
    for (int t = 0; t < TT; t++)
        lstm_step_kernel<<<128, 256>>>(W_hh, t);

    // logits: out[b][t][v] = h_seq[t][b] . fc_W[v] + fc_b[v]
    sgemm_nt_kernel<<<dim3((VV + BN - 1) / BN, (TT * BB) / BM), 256>>>(
        1, fc_W, fc_b, nullptr, out, TT * BB, VV, HH, 1);
}

// round 16
// speedup vs baseline: 2.0555x; 1.6962x over previous
#include <cuda_runtime.h>
#include <cuda_bf16.h>
#include <math.h>

// Problem sizes (fixed by the reference)
#define BB 64      // batch
#define TT 32      // timesteps
#define EE 512     // embed dim
#define HH 512     // hidden
#define H4 2048    // 4*H
#define VV 10000   // vocab

#define KSPLIT 8   // K-split for the recurrence GEMM

// ---------------- scratch (device globals: allocation-free) ----------------
__device__ __align__(16) float g_X[TT * BB * EE];        // [T][B][E]
__device__ __align__(16) float g_xproj[TT * BB * H4];    // [T][B][4H]
__device__ __align__(16) float g_hseq[TT * BB * HH];     // [T][B][H]
__device__ __align__(16) float g_h[BB * HH];
__device__ __align__(16) float g_c[BB * HH];
__device__ __align__(16) float g_gpart[KSPLIT * BB * H4];
__device__ int g_cap64;

// ---------------- captions dtype detection (int32 vs int64) ----------------
// jnp int64 request may silently become int32 without jax x64. For int64
// (values in [0,10000)) every high 32-bit word is 0; for int32 the odd words
// are random caption ids. Reads only the first 2048 int32 words, which is
// within the buffer for either dtype.
__global__ void detect_cap_kernel(const int* __restrict__ cap32) {
    if (threadIdx.x == 0 && blockIdx.x == 0) {
        int acc = 0;
        for (int i = 0; i < 256; i++) acc |= cap32[2 * i + 1];
        g_cap64 = (acc == 0) ? 1 : 0;
    }
}

// ---------------- init h0/c0 = 0 ----------------
__global__ void zero_state_kernel() {
    int i = blockIdx.x * blockDim.x + threadIdx.x;
    if (i < BB * HH) { g_h[i] = 0.0f; g_c[i] = 0.0f; }
}

// ---------------- build X ----------------
__global__ void build_x_kernel(const float* __restrict__ feat,
                               const void* __restrict__ cap,
                               const float* __restrict__ embW) {
    int row = blockIdx.x;            // row = t*B + b
    int t = row >> 6;
    int b = row & 63;
    const float* src;
    if (t == 0) {
        src = feat + (size_t)b * EE;
    } else {
        long long idx;
        if (g_cap64) idx = ((const long long*)cap)[b * TT + t];
        else         idx = (long long)((const int*)cap)[b * TT + t];
        src = embW + (size_t)idx * EE;
    }
    float4* dst = (float4*)(g_X + (size_t)row * EE);
    const float4* s4 = (const float4*)src;
    for (int i = threadIdx.x; i < EE / 4; i += blockDim.x) dst[i] = s4[i];
}

// ---------------- SGEMM NT: C[M,N] = A[M,K] * B[N,K]^T (+ biases) ----------
// asel: 0 -> A = g_X, 1 -> A = g_hseq (device scratch selection)
// mode: 0 -> C row-major [m*N+n]; 1 -> C[(b*T+t)*N+n] with m = t*64+b
#define BM 128
#define BN 128
#define BK 16

__global__ __launch_bounds__(256) void sgemm_nt_kernel(
    int asel, const float* __restrict__ Bm,
    const float* __restrict__ bias1, const float* __restrict__ bias2,
    float* __restrict__ C, int M, int N, int K, int mode)
{
    const float* __restrict__ A = (asel == 0) ? g_X : g_hseq;

    // Row stride BM+4 = 132 floats = 528 bytes: multiple of 16B, so float4
    // reads at &As[buf][kk][8*t] are always 16B-aligned.
    __shared__ float As[2][BK][BM + 4];
    __shared__ float Bs[2][BK][BN + 4];

    const int tid = threadIdx.x;
    const int bm = blockIdx.y * BM;
    const int bn = blockIdx.x * BN;

    const int lr = tid >> 2;           // 0..63
    const int lk = (tid & 3) << 2;     // 0,4,8,12

    const int tx = tid & 15;
    const int ty = tid >> 4;

    float acc[8][8];
#pragma unroll
    for (int i = 0; i < 8; i++)
#pragma unroll
        for (int j = 0; j < 8; j++) acc[i][j] = 0.0f;

    float4 ra0, ra1, rb0, rb1;
    const float4 z4 = make_float4(0.f, 0.f, 0.f, 0.f);

#define FETCH(K0)                                                              \
    do {                                                                       \
        ra0 = *(const float4*)(A + (size_t)(bm + lr) * K + (K0) + lk);         \
        ra1 = *(const float4*)(A + (size_t)(bm + lr + 64) * K + (K0) + lk);    \
        int r0_ = bn + lr, r1_ = bn + lr + 64;                                 \
        rb0 = (r0_ < N) ? *(const float4*)(Bm + (size_t)r0_ * K + (K0) + lk) : z4; \
        rb1 = (r1_ < N) ? *(const float4*)(Bm + (size_t)r1_ * K + (K0) + lk) : z4; \
    } while (0)

#define STAGE(BUF)                                                             \
    do {                                                                       \
        As[BUF][lk + 0][lr] = ra0.x; As[BUF][lk + 1][lr] = ra0.y;              \
        As[BUF][lk + 2][lr] = ra0.z; As[BUF][lk + 3][lr] = ra0.w;              \
        As[BUF][lk + 0][lr + 64] = ra1.x; As[BUF][lk + 1][lr + 64] = ra1.y;    \
        As[BUF][lk + 2][lr + 64] = ra1.z; As[BUF][lk + 3][lr + 64] = ra1.w;    \
        Bs[BUF][lk + 0][lr] = rb0.x; Bs[BUF][lk + 1][lr] = rb0.y;              \
        Bs[BUF][lk + 2][lr] = rb0.z; Bs[BUF][lk + 3][lr] = rb0.w;              \
        Bs[BUF][lk + 0][lr + 64] = rb1.x; Bs[BUF][lk + 1][lr + 64] = rb1.y;    \
        Bs[BUF][lk + 2][lr + 64] = rb1.z; Bs[BUF][lk + 3][lr + 64] = rb1.w;    \
    } while (0)

    FETCH(0);
    STAGE(0);
    __syncthreads();

    const int nk = K / BK;
    for (int kt = 0; kt < nk; kt++) {
        if (kt + 1 < nk) FETCH((kt + 1) * BK);
        const int buf = kt & 1;
#pragma unroll
        for (int kk = 0; kk < BK; kk++) {
            float4 a0 = *(const float4*)&As[buf][kk][ty * 8];
            float4 a1 = *(const float4*)&As[buf][kk][ty * 8 + 4];
            float4 b0 = *(const float4*)&Bs[buf][kk][tx * 8];
            float4 b1 = *(const float4*)&Bs[buf][kk][tx * 8 + 4];
            float av[8] = {a0.x, a0.y, a0.z, a0.w, a1.x, a1.y, a1.z, a1.w};
            float bv[8] = {b0.x, b0.y, b0.z, b0.w, b1.x, b1.y, b1.z, b1.w};
#pragma unroll
            for (int i = 0; i < 8; i++)
#pragma unroll
                for (int j = 0; j < 8; j++) acc[i][j] += av[i] * bv[j];
        }
        if (kt + 1 < nk) {
            __syncthreads();
            STAGE((kt + 1) & 1);
            __syncthreads();
        }
    }

#pragma unroll
    for (int i = 0; i < 8; i++) {
        int m = bm + ty * 8 + i;
        int t = m >> 6;
        int b = m & 63;
#pragma unroll
        for (int j = 0; j < 8; j++) {
            int n = bn + tx * 8 + j;
            if (n < N) {
                float v = acc[i][j];
                if (bias1) v += bias1[n];
                if (bias2) v += bias2[n];
                if (mode == 0) C[(size_t)m * N + n] = v;
                else           C[(size_t)(b * TT + t) * N + n] = v;
            }
        }
    }
#undef FETCH
#undef STAGE
}

// ---------------- LSTM stage 1: K-split partial GEMM -----------------------
// gpart[s][b][g] = sum_{k in chunk s} h[b][k] * W_hh[g][k]
// grid (16, KSPLIT), block 256. Micro-tile 8 batches x 4 gates.
__global__ __launch_bounds__(256) void lstm_part_kernel(const float* __restrict__ Whh)
{
    const int g0 = blockIdx.x * 128;
    const int k0 = blockIdx.y * (HH / KSPLIT);   // 64-wide K chunk
    const int tid = threadIdx.x;
    const int tgx = tid & 31;
    const int tby = tid >> 5;

    // Row strides are multiples of 4 floats (16B) because the compute loop
    // reads these via float4 (R3 fix).
    __shared__ float hs[16][BB + 4];
    __shared__ float ws[16][128 + 4];

    float acc[8][4];
#pragma unroll
    for (int i = 0; i < 8; i++)
#pragma unroll
        for (int j = 0; j < 4; j++) acc[i][j] = 0.0f;

    for (int ks = 0; ks < HH / KSPLIT; ks += 16) {
        for (int i = tid; i < 16 * BB; i += 256) {
            int b = i >> 4, kk = i & 15;
            hs[kk][b] = g_h[b * HH + k0 + ks + kk];
        }
        for (int i = tid; i < 16 * 128; i += 256) {
            int g = i >> 4, kk = i & 15;
            ws[kk][g] = Whh[(size_t)(g0 + g) * HH + k0 + ks + kk];
        }
        __syncthreads();
#pragma unroll
        for (int kk = 0; kk < 16; kk++) {
            float4 wv = *(const float4*)&ws[kk][tgx * 4];
            float4 h0 = *(const float4*)&hs[kk][tby * 8];
            float4 h1 = *(const float4*)&hs[kk][tby * 8 + 4];
            float hv[8] = {h0.x, h0.y, h0.z, h0.w, h1.x, h1.y, h1.z, h1.w};
            float wf[4] = {wv.x, wv.y, wv.z, wv.w};
#pragma unroll
            for (int i = 0; i < 8; i++)
#pragma unroll
                for (int j = 0; j < 4; j++) acc[i][j] += hv[i] * wf[j];
        }
        __syncthreads();
    }

#pragma unroll
    for (int i = 0; i < 8; i++) {
        size_t base = ((size_t)blockIdx.y * BB + (tby * 8 + i)) * H4 + g0 + tgx * 4;
        *(float4*)&g_gpart[base] = make_float4(acc[i][0], acc[i][1], acc[i][2], acc[i][3]);
    }
}

// ---------------- LSTM stage 2: reduce partials + gates + state update -----
__global__ void lstm_update_kernel(int t, int use_part)
{
    int idx = blockIdx.x * blockDim.x + threadIdx.x;
    if (idx >= BB * HH) return;
    int b = idx >> 9;
    int u = idx & 511;

    const float* xp = g_xproj + ((size_t)(t * BB + b)) * H4;
    float gi = xp[u];
    float gf = xp[HH + u];
    float gg = xp[2 * HH + u];
    float go = xp[3 * HH + u];

    if (use_part) {
#pragma unroll
        for (int s = 0; s < KSPLIT; s++) {
            const float* p = g_gpart + ((size_t)s * BB + b) * H4;
            gi += p[u];
            gf += p[HH + u];
            gg += p[2 * HH + u];
            go += p[3 * HH + u];
        }
    }

    float i_g = 1.0f / (1.0f + expf(-gi));
    float f_g = 1.0f / (1.0f + expf(-gf));
    float g_g = tanhf(gg);
    float o_g = 1.0f / (1.0f + expf(-go));

    float c = f_g * g_c[idx] + i_g * g_g;
    float h = o_g * tanhf(c);
    g_c[idx] = c;
    g_h[idx] = h;
    g_hseq[((size_t)(t * BB + b)) * HH + u] = h;
}

// ---------------- launch ----------------
extern "C" void kernel_launch(void* const* d_in, const int* in_sizes, int n_in,
                              void* d_out, int out_size)
{
    const float* features = (const float*)d_in[0];
    const void*  captions = d_in[1];                 // int32 or int64, detected
    const float* embed_W  = (const float*)d_in[2];
    const float* W_ih     = (const float*)d_in[3];
    const float* W_hh     = (const float*)d_in[4];
    const float* b_ih     = (const float*)d_in[5];
    const float* b_hh     = (const float*)d_in[6];
    const float* fc_W     = (const float*)d_in[7];
    const float* fc_b     = (const float*)d_in[8];
    float* out = (float*)d_out;

    // Resolve device address of the g_xproj scratch once (host-side symbol
    // lookup; allocation-free and graph-safe).
    static float* xproj_ptr = nullptr;
    if (!xproj_ptr) {
        void* p = nullptr;
        cudaGetSymbolAddress(&p, g_xproj);
        xproj_ptr = (float*)p;
    }

    detect_cap_kernel<<<1, 32>>>((const int*)captions);
    zero_state_kernel<<<(BB * HH + 255) / 256, 256>>>();
    build_x_kernel<<<TT * BB, 128>>>(features, captions, embed_W);

    // x_proj = X @ W_ih^T + b_ih + b_hh   [T*B, 4H]
    sgemm_nt_kernel<<<dim3(H4 / BN, (TT * BB) / BM), 256>>>(
        0, W_ih, b_ih, b_hh, xproj_ptr, TT * BB, H4, EE, 0);

    for (int t = 0; t < TT; t++) {
        if (t > 0) lstm_part_kernel<<<dim3(H4 / 128, KSPLIT), 256>>>(W_hh);
        lstm_update_kernel<<<(BB * HH + 255) / 256, 256>>>(t, t > 0 ? 1 : 0);
    }

    // logits: out[b][t][v] = h_seq[t][b] . fc_W[v] + fc_b[v]
    sgemm_nt_kernel<<<dim3((VV + BN - 1) / BN, (TT * BB) / BM), 256>>>(
        1, fc_W, fc_b, nullptr, out, TT * BB, VV, HH, 1);
}

// round 17
// speedup vs baseline: 2.1160x; 1.0294x over previous
#include <cuda_runtime.h>
#include <cuda_bf16.h>
#include <math.h>

// Problem sizes (fixed by the reference)
#define BB 64      // batch
#define TT 32      // timesteps
#define EE 512     // embed dim
#define HH 512     // hidden
#define H4 2048    // 4*H
#define VV 10000   // vocab

#define KSPLIT 8   // K-split for the recurrence GEMM

// ---------------- scratch (device globals: allocation-free) ----------------
__device__ __align__(16) float g_X[TT * BB * EE];        // [T][B][E]
__device__ __align__(16) float g_xproj[TT * BB * H4];    // [T][B][4H]
__device__ __align__(16) float g_hseq[TT * BB * HH];     // [T][B][H]
__device__ __align__(16) float g_h[BB * HH];
__device__ __align__(16) float g_c[BB * HH];
__device__ __align__(16) float g_gpart[KSPLIT * BB * H4];
__device__ int g_cap64;

// ---------------- captions dtype detection (int32 vs int64) ----------------
// For int64 (values in [0,10000)) every high 32-bit word is 0; for int32 the
// odd words are random caption ids. Reads only the first 2048 int32 words,
// in-bounds for either dtype.
__global__ void detect_cap_kernel(const int* __restrict__ cap32) {
    if (threadIdx.x == 0 && blockIdx.x == 0) {
        int acc = 0;
        for (int i = 0; i < 256; i++) acc |= cap32[2 * i + 1];
        g_cap64 = (acc == 0) ? 1 : 0;
    }
}

// ---------------- init h0/c0 = 0 ----------------
__global__ void zero_state_kernel() {
    int i = blockIdx.x * blockDim.x + threadIdx.x;
    if (i < BB * HH) { g_h[i] = 0.0f; g_c[i] = 0.0f; }
}

// ---------------- build X ----------------
__global__ void build_x_kernel(const float* __restrict__ feat,
                               const void* __restrict__ cap,
                               const float* __restrict__ embW) {
    int row = blockIdx.x;            // row = t*B + b
    int t = row >> 6;
    int b = row & 63;
    const float* src;
    if (t == 0) {
        src = feat + (size_t)b * EE;
    } else {
        long long idx;
        if (g_cap64) idx = ((const long long*)cap)[b * TT + t];
        else         idx = (long long)((const int*)cap)[b * TT + t];
        src = embW + (size_t)idx * EE;
    }
    float4* dst = (float4*)(g_X + (size_t)row * EE);
    const float4* s4 = (const float4*)src;
    for (int i = threadIdx.x; i < EE / 4; i += blockDim.x) dst[i] = s4[i];
}

// ---------------- SGEMM NT: C[M,N] = A[M,K] * B[N,K]^T (+ biases) ----------
// R17 single-variable change vs the measured R5/R16 kernel: BM 128 -> 64
// with 128 threads. The per-thread inner loop / microtile / LDS pattern is
// byte-identical (8x8 acc, float4 smem reads). Regs/CTA drop 35.6K -> ~19K
// -> 3 CTAs/SM = 12 warps (was 1 CTA / 8 warps, occ 12.5%, issue 53.4%:
// latency-bound). Occupancy comes from CTA size, NOT a reg clamp (R5's
// spill lesson).
// asel: 0 -> A = g_X, 1 -> A = g_hseq.
// mode: 0 -> C[m*N+n]; 1 -> C[(b*TT+t)*N+n] with m = t*64+b.
#define BM 64
#define BN 128
#define BK 16

__global__ __launch_bounds__(128) void sgemm_nt_kernel(
    int asel, const float* __restrict__ Bm,
    const float* __restrict__ bias1, const float* __restrict__ bias2,
    float* __restrict__ C, int M, int N, int K, int mode)
{
    const float* __restrict__ A = (asel == 0) ? g_X : g_hseq;

    // Row strides 68/132 floats = 272B/528B: 16B multiples, float4-safe.
    __shared__ float As[2][BK][BM + 4];
    __shared__ float Bs[2][BK][BN + 4];

    const int tid = threadIdx.x;
    const int bm = blockIdx.y * BM;
    const int bn = blockIdx.x * BN;

    // A loader: 128 threads x 2 float4 = 64 rows x 16 k
    const int ar = tid >> 1;           // 0..63
    const int ak = (tid & 1) << 3;     // 0, 8
    // B loader: 128 threads x 4 float4 = 128 rows x 16 k
    const int br = tid >> 2;           // 0..31 (rows br, +32, +64, +96)
    const int bk = (tid & 3) << 2;     // 0,4,8,12

    // compute mapping: 8(M-groups) x 16(N-groups), 8x8 micro-tile
    const int tx = tid & 15;
    const int ty = tid >> 4;           // 0..7

    float acc[8][8];
#pragma unroll
    for (int i = 0; i < 8; i++)
#pragma unroll
        for (int j = 0; j < 8; j++) acc[i][j] = 0.0f;

    float4 ra0, ra1, rb0, rb1, rb2, rb3;
    const float4 z4 = make_float4(0.f, 0.f, 0.f, 0.f);

#define FETCH(K0)                                                              \
    do {                                                                       \
        ra0 = *(const float4*)(A + (size_t)(bm + ar) * K + (K0) + ak);         \
        ra1 = *(const float4*)(A + (size_t)(bm + ar) * K + (K0) + ak + 4);     \
        int r0_ = bn + br, r1_ = bn + br + 32,                                 \
            r2_ = bn + br + 64, r3_ = bn + br + 96;                            \
        rb0 = (r0_ < N) ? *(const float4*)(Bm + (size_t)r0_ * K + (K0) + bk) : z4; \
        rb1 = (r1_ < N) ? *(const float4*)(Bm + (size_t)r1_ * K + (K0) + bk) : z4; \
        rb2 = (r2_ < N) ? *(const float4*)(Bm + (size_t)r2_ * K + (K0) + bk) : z4; \
        rb3 = (r3_ < N) ? *(const float4*)(Bm + (size_t)r3_ * K + (K0) + bk) : z4; \
    } while (0)

#define STAGE(BUF)                                                             \
    do {                                                                       \
        As[BUF][ak + 0][ar] = ra0.x; As[BUF][ak + 1][ar] = ra0.y;              \
        As[BUF][ak + 2][ar] = ra0.z; As[BUF][ak + 3][ar] = ra0.w;              \
        As[BUF][ak + 4][ar] = ra1.x; As[BUF][ak + 5][ar] = ra1.y;              \
        As[BUF][ak + 6][ar] = ra1.z; As[BUF][ak + 7][ar] = ra1.w;              \
        Bs[BUF][bk + 0][br] = rb0.x; Bs[BUF][bk + 1][br] = rb0.y;              \
        Bs[BUF][bk + 2][br] = rb0.z; Bs[BUF][bk + 3][br] = rb0.w;              \
        Bs[BUF][bk + 0][br + 32] = rb1.x; Bs[BUF][bk + 1][br + 32] = rb1.y;    \
        Bs[BUF][bk + 2][br + 32] = rb1.z; Bs[BUF][bk + 3][br + 32] = rb1.w;    \
        Bs[BUF][bk + 0][br + 64] = rb2.x; Bs[BUF][bk + 1][br + 64] = rb2.y;    \
        Bs[BUF][bk + 2][br + 64] = rb2.z; Bs[BUF][bk + 3][br + 64] = rb2.w;    \
        Bs[BUF][bk + 0][br + 96] = rb3.x; Bs[BUF][bk + 1][br + 96] = rb3.y;    \
        Bs[BUF][bk + 2][br + 96] = rb3.z; Bs[BUF][bk + 3][br + 96] = rb3.w;    \
    } while (0)

    FETCH(0);
    STAGE(0);
    __syncthreads();

    const int nk = K / BK;
    for (int kt = 0; kt < nk; kt++) {
        if (kt + 1 < nk) FETCH((kt + 1) * BK);
        const int buf = kt & 1;
#pragma unroll
        for (int kk = 0; kk < BK; kk++) {
            float4 a0 = *(const float4*)&As[buf][kk][ty * 8];
            float4 a1 = *(const float4*)&As[buf][kk][ty * 8 + 4];
            float4 b0 = *(const float4*)&Bs[buf][kk][tx * 8];
            float4 b1 = *(const float4*)&Bs[buf][kk][tx * 8 + 4];
            float av[8] = {a0.x, a0.y, a0.z, a0.w, a1.x, a1.y, a1.z, a1.w};
            float bv[8] = {b0.x, b0.y, b0.z, b0.w, b1.x, b1.y, b1.z, b1.w};
#pragma unroll
            for (int i = 0; i < 8; i++)
#pragma unroll
                for (int j = 0; j < 8; j++) acc[i][j] += av[i] * bv[j];
        }
        if (kt + 1 < nk) {
            __syncthreads();
            STAGE((kt + 1) & 1);
            __syncthreads();
        }
    }

#pragma unroll
    for (int i = 0; i < 8; i++) {
        int m = bm + ty * 8 + i;
        int t = m >> 6;
        int b = m & 63;
#pragma unroll
        for (int j = 0; j < 8; j++) {
            int n = bn + tx * 8 + j;
            if (n < N) {
                float v = acc[i][j];
                if (bias1) v += bias1[n];
                if (bias2) v += bias2[n];
                if (mode == 0) C[(size_t)m * N + n] = v;
                else           C[(size_t)(b * TT + t) * N + n] = v;
            }
        }
    }
#undef FETCH
#undef STAGE
}

// ---------------- LSTM stage 1: K-split partial GEMM (R16-identical) -------
__global__ __launch_bounds__(256) void lstm_part_kernel(const float* __restrict__ Whh)
{
    const int g0 = blockIdx.x * 128;
    const int k0 = blockIdx.y * (HH / KSPLIT);   // 64-wide K chunk
    const int tid = threadIdx.x;
    const int tgx = tid & 31;
    const int tby = tid >> 5;

    __shared__ float hs[16][BB + 4];
    __shared__ float ws[16][128 + 4];

    float acc[8][4];
#pragma unroll
    for (int i = 0; i < 8; i++)
#pragma unroll
        for (int j = 0; j < 4; j++) acc[i][j] = 0.0f;

    for (int ks = 0; ks < HH / KSPLIT; ks += 16) {
        for (int i = tid; i < 16 * BB; i += 256) {
            int b = i >> 4, kk = i & 15;
            hs[kk][b] = g_h[b * HH + k0 + ks + kk];
        }
        for (int i = tid; i < 16 * 128; i += 256) {
            int g = i >> 4, kk = i & 15;
            ws[kk][g] = Whh[(size_t)(g0 + g) * HH + k0 + ks + kk];
        }
        __syncthreads();
#pragma unroll
        for (int kk = 0; kk < 16; kk++) {
            float4 wv = *(const float4*)&ws[kk][tgx * 4];
            float4 h0 = *(const float4*)&hs[kk][tby * 8];
            float4 h1 = *(const float4*)&hs[kk][tby * 8 + 4];
            float hv[8] = {h0.x, h0.y, h0.z, h0.w, h1.x, h1.y, h1.z, h1.w};
            float wf[4] = {wv.x, wv.y, wv.z, wv.w};
#pragma unroll
            for (int i = 0; i < 8; i++)
#pragma unroll
                for (int j = 0; j < 4; j++) acc[i][j] += hv[i] * wf[j];
        }
        __syncthreads();
    }

#pragma unroll
    for (int i = 0; i < 8; i++) {
        size_t base = ((size_t)blockIdx.y * BB + (tby * 8 + i)) * H4 + g0 + tgx * 4;
        *(float4*)&g_gpart[base] = make_float4(acc[i][0], acc[i][1], acc[i][2], acc[i][3]);
    }
}

// ---------------- LSTM stage 2: reduce + gates + update (R16-identical) ----
__global__ void lstm_update_kernel(int t, int use_part)
{
    int idx = blockIdx.x * blockDim.x + threadIdx.x;
    if (idx >= BB * HH) return;
    int b = idx >> 9;
    int u = idx & 511;

    const float* xp = g_xproj + ((size_t)(t * BB + b)) * H4;
    float gi = xp[u];
    float gf = xp[HH + u];
    float gg = xp[2 * HH + u];
    float go = xp[3 * HH + u];

    if (use_part) {
#pragma unroll
        for (int s = 0; s < KSPLIT; s++) {
            const float* p = g_gpart + ((size_t)s * BB + b) * H4;
            gi += p[u];
            gf += p[HH + u];
            gg += p[2 * HH + u];
            go += p[3 * HH + u];
        }
    }

    float i_g = 1.0f / (1.0f + expf(-gi));
    float f_g = 1.0f / (1.0f + expf(-gf));
    float g_g = tanhf(gg);
    float o_g = 1.0f / (1.0f + expf(-go));

    float c = f_g * g_c[idx] + i_g * g_g;
    float h = o_g * tanhf(c);
    g_c[idx] = c;
    g_h[idx] = h;
    g_hseq[((size_t)(t * BB + b)) * HH + u] = h;
}

// ---------------- launch ----------------
extern "C" void kernel_launch(void* const* d_in, const int* in_sizes, int n_in,
                              void* d_out, int out_size)
{
    const float* features = (const float*)d_in[0];
    const void*  captions = d_in[1];                 // int32 or int64, detected
    const float* embed_W  = (const float*)d_in[2];
    const float* W_ih     = (const float*)d_in[3];
    const float* W_hh     = (const float*)d_in[4];
    const float* b_ih     = (const float*)d_in[5];
    const float* b_hh     = (const float*)d_in[6];
    const float* fc_W     = (const float*)d_in[7];
    const float* fc_b     = (const float*)d_in[8];
    float* out = (float*)d_out;

    // Resolve device address of g_xproj once (host-side symbol lookup;
    // allocation-free, graph-safe).
    static float* xproj_ptr = nullptr;
    if (!xproj_ptr) {
        void* p = nullptr;
        cudaGetSymbolAddress(&p, g_xproj);
        xproj_ptr = (float*)p;
    }

    detect_cap_kernel<<<1, 32>>>((const int*)captions);
    zero_state_kernel<<<(BB * HH + 255) / 256, 256>>>();
    build_x_kernel<<<TT * BB, 128>>>(features, captions, embed_W);

    // x_proj = X @ W_ih^T + b_ih + b_hh   [T*B, 4H]
    sgemm_nt_kernel<<<dim3(H4 / BN, (TT * BB) / BM), 128>>>(
        0, W_ih, b_ih, b_hh, xproj_ptr, TT * BB, H4, EE, 0);

    for (int t = 0; t < TT; t++) {
        if (t > 0) lstm_part_kernel<<<dim3(H4 / 128, KSPLIT), 256>>>(W_hh);
        lstm_update_kernel<<<(BB * HH + 255) / 256, 256>>>(t, t > 0 ? 1 : 0);
    }

    // logits: out[b][t][v] = h_seq[t][b] . fc_W[v] + fc_b[v]
    sgemm_nt_kernel<<<dim3((VV + BN - 1) / BN, (TT * BB) / BM), 128>>>(
        1, fc_W, fc_b, nullptr, out, TT * BB, VV, HH, 1);
}